// round 14
// baseline (speedup 1.0000x reference)
#include <cuda_runtime.h>
#include <cuda_fp16.h>
#include <math.h>

#define B_ 2
#define S_ 2048
#define D_ 1024
#define H_ 16
#define HD_ 64

// ---------------- scratch ----------------
__device__ float  g_ada[B_ * 6 * D_];
__device__ __half g_h[(size_t)B_ * S_ * D_];
__device__ __half g_qkh[(size_t)B_ * S_ * 2 * D_];           // Q(scaled by log2e/8),K fp16
__device__ __half g_vt[(size_t)B_ * H_ * HD_ * S_];          // V^T fp16
__device__ __half g_attn2[(size_t)B_ * S_ * D_];
__device__ float  g_x1[(size_t)B_ * S_ * D_];
__device__ __half g_mlp[(size_t)B_ * S_ * 4 * D_];
__device__ __half g_wqkv[(size_t)3 * D_ * D_];
__device__ __half g_wout[(size_t)D_ * D_];
__device__ __half g_w1[(size_t)4 * D_ * D_];
__device__ __half g_w2[(size_t)4 * D_ * D_];

__device__ __forceinline__ float gelu_tanh(float v) {
    float u = 0.7978845608028654f * (v + 0.044715f * v * v * v);
    return 0.5f * v * (1.f + tanhf(u));
}

__device__ __forceinline__ void cp16(void* s, const void* g) {
    unsigned sa = (unsigned)__cvta_generic_to_shared(s);
    asm volatile("cp.async.cg.shared.global [%0], [%1], 16;" :: "r"(sa), "l"(g));
}
#define CP_COMMIT() asm volatile("cp.async.commit_group;")
#define CP_WAIT(n)  asm volatile("cp.async.wait_group %0;" :: "n"(n))

#define MMA16(d0,d1,d2,d3,a0,a1,a2,a3,b0,b1) \
    asm volatile( \
        "mma.sync.aligned.m16n8k16.row.col.f32.f16.f16.f32 " \
        "{%0,%1,%2,%3}, {%4,%5,%6,%7}, {%8,%9}, {%0,%1,%2,%3};" \
        : "+f"(d0), "+f"(d1), "+f"(d2), "+f"(d3) \
        : "r"(a0), "r"(a1), "r"(a2), "r"(a3), "r"(b0), "r"(b1))

__device__ __forceinline__ uint4 ldsm4(const __half* p) {
    uint4 r;
    unsigned a = (unsigned)__cvta_generic_to_shared(p);
    asm volatile("ldmatrix.sync.aligned.m8n8.x4.shared.b16 {%0,%1,%2,%3}, [%4];"
                 : "=r"(r.x), "=r"(r.y), "=r"(r.z), "=r"(r.w) : "r"(a));
    return r;
}

// ---------------- convert all weights fp32 -> fp16 (one launch) ----------------
__global__ void conv_all(const float* __restrict__ wq, const float* __restrict__ wo,
                         const float* __restrict__ w1, const float* __restrict__ w2,
                         __half* __restrict__ oq, __half* __restrict__ oo,
                         __half* __restrict__ o1, __half* __restrict__ o2)
{
    const long n_q = 3L * D_ * D_ / 4, n_o = (long)D_ * D_ / 4, n_m = (long)D_ * D_;
    long i = (long)blockIdx.x * 256 + threadIdx.x;
    const float* src; __half* dst; long off;
    if (i < n_q)                  { src = wq; dst = oq; off = i; }
    else if (i < n_q + n_o)       { src = wo; dst = oo; off = i - n_q; }
    else if (i < n_q + n_o + n_m) { src = w1; dst = o1; off = i - n_q - n_o; }
    else                          { src = w2; dst = o2; off = i - n_q - n_o - n_m; }
    float4 v = reinterpret_cast<const float4*>(src)[off];
    reinterpret_cast<__half2*>(dst)[off * 2]     = __floats2half2_rn(v.x, v.y);
    reinterpret_cast<__half2*>(dst)[off * 2 + 1] = __floats2half2_rn(v.z, v.w);
}

// ============================================================================
// Fused flash attention, fp16 mma + ldmatrix, base-2 softmax.
// Q tile 128 rows, 256 threads = 8 warps, 2 CTAs/SM.
// ============================================================================
#define FA_SMEM 73728

__global__ void __launch_bounds__(256, 2) flash_attn(
    const __half* __restrict__ qkh, const __half* __restrict__ vt,
    __half* __restrict__ out)
{
    extern __shared__ __half sm[];
    __half* Qs  = sm;                       // [128][72]
    __half* Ks  = sm + 9216;                // [2][64][72]
    __half* Vs  = sm + 18432;               // [2][64][72]
    __half* Psw = sm + 27648;               // 8 x [16][72]

    const int tid  = threadIdx.x;
    const int lane = tid & 31;
    const int warp = tid >> 5;
    const int grp  = lane >> 2;
    const int tig  = lane & 3;
    const int b    = blockIdx.y >> 4;
    const int h    = blockIdx.y & 15;
    const int qBase = blockIdx.x * 128;

    const int rA = (lane & 7) + ((lane >> 3) & 1) * 8;
    const int cA = ((lane >> 4) & 1) * 8;
    const int rB = (lane & 7) + ((lane >> 4) & 1) * 8;
    const int cB = ((lane >> 3) & 1) * 8;

    const __half* vth = vt + ((long)(b * H_ + h) * HD_) * S_;

#pragma unroll
    for (int i = 0; i < 4; i++) {
        int idx = tid + i * 256;
        int r   = idx >> 3;
        int q8  = idx & 7;
        cp16(&Qs[r * 72 + q8 * 8],
             &qkh[((long)(b * S_ + qBase + r)) * 2048 + h * 64 + q8 * 8]);
    }
#pragma unroll
    for (int i = 0; i < 2; i++) {
        int idx = tid + i * 256;
        int r   = idx >> 3;
        int q8  = idx & 7;
        cp16(&Ks[r * 72 + q8 * 8],
             &qkh[((long)(b * S_ + r)) * 2048 + 1024 + h * 64 + q8 * 8]);
        cp16(&Vs[r * 72 + q8 * 8], &vth[(long)r * S_ + q8 * 8]);
    }
    CP_COMMIT();

    __half* Ps = Psw + warp * 16 * 72;
    const __half* Qw = Qs + warp * 16 * 72;

    float m0 = -INFINITY, m1 = -INFINITY, l0 = 0.f, l1 = 0.f;
    float o[8][4];
#pragma unroll
    for (int j = 0; j < 8; j++)
#pragma unroll
        for (int t = 0; t < 4; t++) o[j][t] = 0.f;

    const int nT = S_ / 64;
    for (int t = 0; t < nT; t++) {
        CP_WAIT(0);
        __syncthreads();

        if (t + 1 < nT) {
            __half* Kn = Ks + ((t + 1) & 1) * 4608;
            __half* Vn = Vs + ((t + 1) & 1) * 4608;
            int kt = (t + 1) * 64;
#pragma unroll
            for (int i = 0; i < 2; i++) {
                int idx = tid + i * 256;
                int r   = idx >> 3;
                int q8  = idx & 7;
                cp16(&Kn[r * 72 + q8 * 8],
                     &qkh[((long)(b * S_ + kt + r)) * 2048 + 1024 + h * 64 + q8 * 8]);
                cp16(&Vn[r * 72 + q8 * 8], &vth[(long)r * S_ + kt + q8 * 8]);
            }
        }
        CP_COMMIT();

        const __half* Kc = Ks + (t & 1) * 4608;
        const __half* Vc = Vs + (t & 1) * 4608;

        float s[8][4];
#pragma unroll
        for (int j = 0; j < 8; j++)
#pragma unroll
            for (int tt = 0; tt < 4; tt++) s[j][tt] = 0.f;

#pragma unroll
        for (int kk = 0; kk < 64; kk += 16) {
            uint4 aq = ldsm4(&Qw[rA * 72 + kk + cA]);
#pragma unroll
            for (int jp = 0; jp < 4; jp++) {
                uint4 bk = ldsm4(&Kc[(jp * 16 + rB) * 72 + kk + cB]);
                MMA16(s[2*jp][0],   s[2*jp][1],   s[2*jp][2],   s[2*jp][3],
                      aq.x, aq.y, aq.z, aq.w, bk.x, bk.y);
                MMA16(s[2*jp+1][0], s[2*jp+1][1], s[2*jp+1][2], s[2*jp+1][3],
                      aq.x, aq.y, aq.z, aq.w, bk.z, bk.w);
            }
        }

        float mx0 = -INFINITY, mx1 = -INFINITY;
#pragma unroll
        for (int j = 0; j < 8; j++) {
            mx0 = fmaxf(mx0, fmaxf(s[j][0], s[j][1]));
            mx1 = fmaxf(mx1, fmaxf(s[j][2], s[j][3]));
        }
        mx0 = fmaxf(mx0, __shfl_xor_sync(0xffffffffu, mx0, 1));
        mx0 = fmaxf(mx0, __shfl_xor_sync(0xffffffffu, mx0, 2));
        mx1 = fmaxf(mx1, __shfl_xor_sync(0xffffffffu, mx1, 1));
        mx1 = fmaxf(mx1, __shfl_xor_sync(0xffffffffu, mx1, 2));
        float mn0 = fmaxf(m0, mx0), mn1 = fmaxf(m1, mx1);
        float sc0 = exp2f(m0 - mn0), sc1 = exp2f(m1 - mn1);

        float sum0 = 0.f, sum1 = 0.f;
#pragma unroll
        for (int j = 0; j < 8; j++) {
            float p0 = exp2f(s[j][0] - mn0);
            float p1 = exp2f(s[j][1] - mn0);
            float p2 = exp2f(s[j][2] - mn1);
            float p3 = exp2f(s[j][3] - mn1);
            sum0 += p0 + p1; sum1 += p2 + p3;
            *reinterpret_cast<__half2*>(&Ps[grp * 72 + j * 8 + tig * 2]) =
                __floats2half2_rn(p0, p1);
            *reinterpret_cast<__half2*>(&Ps[(grp + 8) * 72 + j * 8 + tig * 2]) =
                __floats2half2_rn(p2, p3);
        }
        sum0 += __shfl_xor_sync(0xffffffffu, sum0, 1);
        sum0 += __shfl_xor_sync(0xffffffffu, sum0, 2);
        sum1 += __shfl_xor_sync(0xffffffffu, sum1, 1);
        sum1 += __shfl_xor_sync(0xffffffffu, sum1, 2);
        l0 = l0 * sc0 + sum0;
        l1 = l1 * sc1 + sum1;
        m0 = mn0; m1 = mn1;

#pragma unroll
        for (int j = 0; j < 8; j++) {
            o[j][0] *= sc0; o[j][1] *= sc0;
            o[j][2] *= sc1; o[j][3] *= sc1;
        }
        __syncwarp();

#pragma unroll
        for (int kk = 0; kk < 64; kk += 16) {
            uint4 ap = ldsm4(&Ps[rA * 72 + kk + cA]);
#pragma unroll
            for (int jp = 0; jp < 4; jp++) {
                uint4 bv = ldsm4(&Vc[(jp * 16 + rB) * 72 + kk + cB]);
                MMA16(o[2*jp][0],   o[2*jp][1],   o[2*jp][2],   o[2*jp][3],
                      ap.x, ap.y, ap.z, ap.w, bv.x, bv.y);
                MMA16(o[2*jp+1][0], o[2*jp+1][1], o[2*jp+1][2], o[2*jp+1][3],
                      ap.x, ap.y, ap.z, ap.w, bv.z, bv.w);
            }
        }
        __syncwarp();
    }

    float inv0 = 1.f / l0, inv1 = 1.f / l1;
    int row0 = qBase + warp * 16 + grp;
#pragma unroll
    for (int j = 0; j < 8; j++) {
        int col = h * 64 + j * 8 + tig * 2;
        *reinterpret_cast<__half2*>(&out[((long)(b * S_ + row0)) * D_ + col]) =
            __floats2half2_rn(o[j][0] * inv0, o[j][1] * inv0);
        *reinterpret_cast<__half2*>(&out[((long)(b * S_ + row0 + 8)) * D_ + col]) =
            __floats2half2_rn(o[j][2] * inv1, o[j][3] * inv1);
    }
}

// ============================================================================
// FP16 NT GEMM, CTA tile 128x128 (qkv / mlp1). 4-stage cp.async, ldmatrix.
// ============================================================================
#define GSTAGES 4
#define GEMM_SMEM (GSTAGES * 128 * 40 * 2 * 2)   // 81920 B

__global__ void __launch_bounds__(256, 2) gemm_nt_f16(
    const __half* __restrict__ A, const __half* __restrict__ B, void* __restrict__ Cv,
    int K, int lda, int ldb, int ldc,
    int mode, const float* __restrict__ EX, const float* __restrict__ evec,
    const float* __restrict__ ada, int adaOff,
    __half* __restrict__ qh, __half* __restrict__ vth)
{
    extern __shared__ __half hsm[];
    __half* Asm = hsm;
    __half* Bsm = hsm + GSTAGES * 128 * 40;

    const int tid   = threadIdx.x;
    const int lane  = tid & 31;
    const int warp  = tid >> 5;
    const int warpM = warp & 1;
    const int warpN = warp >> 1;
    const int grp   = lane >> 2;
    const int tig   = lane & 3;

    const int rowBase = blockIdx.y * 128;
    const int colBase = blockIdx.x * 128;

    const int rA = (lane & 7) + ((lane >> 3) & 1) * 8;
    const int cA = ((lane >> 4) & 1) * 8;
    const int rB = (lane & 7) + ((lane >> 4) & 1) * 8;
    const int cB = ((lane >> 3) & 1) * 8;

    float acc[4][4][4];
#pragma unroll
    for (int i = 0; i < 4; i++)
#pragma unroll
        for (int j = 0; j < 4; j++)
#pragma unroll
            for (int t = 0; t < 4; t++) acc[i][j][t] = 0.f;

    const int nCh = K >> 5;

    auto load_chunk = [&](int c, int st) {
        __half* as = Asm + st * 128 * 40;
        __half* bs = Bsm + st * 128 * 40;
#pragma unroll
        for (int it = 0; it < 2; it++) {
            int s = tid + it * 256;
            int r = s >> 2;
            int q = s & 3;
            cp16(&as[r * 40 + q * 8], A + (long)(rowBase + r) * lda + c * 32 + q * 8);
            cp16(&bs[r * 40 + q * 8], B + (long)(colBase + r) * ldb + c * 32 + q * 8);
        }
    };

#pragma unroll
    for (int s = 0; s < GSTAGES - 1; s++) {
        if (s < nCh) load_chunk(s, s);
        CP_COMMIT();
    }

    int st = 0;
    for (int c = 0; c < nCh; c++) {
        CP_WAIT(GSTAGES - 2);
        __syncthreads();

        int nc = c + GSTAGES - 1;
        if (nc < nCh) load_chunk(nc, nc % GSTAGES);
        CP_COMMIT();

        const __half* as = Asm + st * 128 * 40;
        const __half* bs = Bsm + st * 128 * 40;
#pragma unroll
        for (int kb = 0; kb < 2; kb++) {
            const int kk = kb * 16;
            uint4 af[4], bf[2];
#pragma unroll
            for (int i = 0; i < 4; i++)
                af[i] = ldsm4(&as[(warpM * 64 + i * 16 + rA) * 40 + kk + cA]);
#pragma unroll
            for (int jp = 0; jp < 2; jp++)
                bf[jp] = ldsm4(&bs[(warpN * 32 + jp * 16 + rB) * 40 + kk + cB]);
#pragma unroll
            for (int i = 0; i < 4; i++) {
                MMA16(acc[i][0][0], acc[i][0][1], acc[i][0][2], acc[i][0][3],
                      af[i].x, af[i].y, af[i].z, af[i].w, bf[0].x, bf[0].y);
                MMA16(acc[i][1][0], acc[i][1][1], acc[i][1][2], acc[i][1][3],
                      af[i].x, af[i].y, af[i].z, af[i].w, bf[0].z, bf[0].w);
                MMA16(acc[i][2][0], acc[i][2][1], acc[i][2][2], acc[i][2][3],
                      af[i].x, af[i].y, af[i].z, af[i].w, bf[1].x, bf[1].y);
                MMA16(acc[i][3][0], acc[i][3][1], acc[i][3][2], acc[i][3][3],
                      af[i].x, af[i].y, af[i].z, af[i].w, bf[1].z, bf[1].w);
            }
        }
        st = (st + 1 == GSTAGES) ? 0 : st + 1;
    }

    float* Cf = (float*)Cv;
    __half* Ch = (__half*)Cv;
#pragma unroll
    for (int i = 0; i < 4; i++) {
#pragma unroll
        for (int j = 0; j < 4; j++) {
            long row = rowBase + warpM * 64 + i * 16 + grp;
            int col = colBase + warpN * 32 + j * 8 + tig * 2;
#pragma unroll
            for (int half_ = 0; half_ < 2; half_++) {
                long r = row + half_ * 8;
                float v0 = acc[i][j][half_ * 2];
                float v1 = acc[i][j][half_ * 2 + 1];
                if (mode == 4) {
                    if (col < 2048) {
                        float qs = (col < 1024) ? 0.18033688011112042f : 1.f;
                        *reinterpret_cast<__half2*>(&qh[r * 2048 + col]) =
                            __floats2half2_rn(v0 * qs, v1 * qs);
                    } else {
                        int hh = (col - 2048) >> 6;
                        int hd = (col - 2048) & 63;
                        int bb = (int)(r >> 11), ss = (int)(r & 2047);
                        __half* base = vth + (((long)(bb * H_ + hh) * HD_ + hd)) * S_ + ss;
                        base[0]  = __float2half_rn(v0);
                        base[S_] = __float2half_rn(v1);
                    }
                } else {  // mode 1 (gelu->half), only other use of this kernel
                    *reinterpret_cast<__half2*>(&Ch[r * ldc + col]) =
                        __floats2half2_rn(gelu_tanh(v0 + evec[col]),
                                          gelu_tanh(v1 + evec[col + 1]));
                }
            }
        }
    }
}

// ============================================================================
// FP16 NT GEMM, CTA tile 64x128 (out-proj / mlp2) for wave-fill.
// 256 threads, 8 warps of 32x32; 4-stage cp.async; 2 CTAs/SM.
// mode 2: EX + ada*v ; mode 3: EX + ada*(v + evec). fp32 output.
// smem: A 4x64x40 + B 4x128x40 halves = 61440 B
// ============================================================================
#define GEMM64_SMEM (GSTAGES * (64 + 128) * 40 * 2)

__global__ void __launch_bounds__(256, 2) gemm_nt_f16_m64(
    const __half* __restrict__ A, const __half* __restrict__ B, float* __restrict__ Cf,
    int K, int lda, int ldb, int ldc,
    int mode, const float* __restrict__ EX, const float* __restrict__ evec,
    const float* __restrict__ ada, int adaOff)
{
    extern __shared__ __half hsm[];
    __half* Asm = hsm;                            // [GSTAGES][64][40]
    __half* Bsm = hsm + GSTAGES * 64 * 40;        // [GSTAGES][128][40]

    const int tid   = threadIdx.x;
    const int lane  = tid & 31;
    const int warp  = tid >> 5;
    const int warpM = warp & 1;                   // 2 warps along M (32 rows each)
    const int warpN = warp >> 1;                  // 4 warps along N (32 cols each)
    const int grp   = lane >> 2;
    const int tig   = lane & 3;

    const int rowBase = blockIdx.y * 64;
    const int colBase = blockIdx.x * 128;

    const int rA = (lane & 7) + ((lane >> 3) & 1) * 8;
    const int cA = ((lane >> 4) & 1) * 8;
    const int rB = (lane & 7) + ((lane >> 4) & 1) * 8;
    const int cB = ((lane >> 3) & 1) * 8;

    float acc[2][4][4];
#pragma unroll
    for (int i = 0; i < 2; i++)
#pragma unroll
        for (int j = 0; j < 4; j++)
#pragma unroll
            for (int t = 0; t < 4; t++) acc[i][j][t] = 0.f;

    const int nCh = K >> 5;

    auto load_chunk = [&](int c, int st) {
        __half* as = Asm + st * 64 * 40;
        __half* bs = Bsm + st * 128 * 40;
        {
            int r = tid >> 2;                     // 0..63
            int q = tid & 3;
            cp16(&as[r * 40 + q * 8], A + (long)(rowBase + r) * lda + c * 32 + q * 8);
        }
#pragma unroll
        for (int it = 0; it < 2; it++) {
            int s = tid + it * 256;
            int r = s >> 2;                       // 0..127
            int q = s & 3;
            cp16(&bs[r * 40 + q * 8], B + (long)(colBase + r) * ldb + c * 32 + q * 8);
        }
    };

#pragma unroll
    for (int s = 0; s < GSTAGES - 1; s++) {
        if (s < nCh) load_chunk(s, s);
        CP_COMMIT();
    }

    int st = 0;
    for (int c = 0; c < nCh; c++) {
        CP_WAIT(GSTAGES - 2);
        __syncthreads();

        int nc = c + GSTAGES - 1;
        if (nc < nCh) load_chunk(nc, nc % GSTAGES);
        CP_COMMIT();

        const __half* as = Asm + st * 64 * 40;
        const __half* bs = Bsm + st * 128 * 40;
#pragma unroll
        for (int kb = 0; kb < 2; kb++) {
            const int kk = kb * 16;
            uint4 af[2], bf[2];
#pragma unroll
            for (int i = 0; i < 2; i++)
                af[i] = ldsm4(&as[(warpM * 32 + i * 16 + rA) * 40 + kk + cA]);
#pragma unroll
            for (int jp = 0; jp < 2; jp++)
                bf[jp] = ldsm4(&bs[(warpN * 32 + jp * 16 + rB) * 40 + kk + cB]);
#pragma unroll
            for (int i = 0; i < 2; i++) {
                MMA16(acc[i][0][0], acc[i][0][1], acc[i][0][2], acc[i][0][3],
                      af[i].x, af[i].y, af[i].z, af[i].w, bf[0].x, bf[0].y);
                MMA16(acc[i][1][0], acc[i][1][1], acc[i][1][2], acc[i][1][3],
                      af[i].x, af[i].y, af[i].z, af[i].w, bf[0].z, bf[0].w);
                MMA16(acc[i][2][0], acc[i][2][1], acc[i][2][2], acc[i][2][3],
                      af[i].x, af[i].y, af[i].z, af[i].w, bf[1].x, bf[1].y);
                MMA16(acc[i][3][0], acc[i][3][1], acc[i][3][2], acc[i][3][3],
                      af[i].x, af[i].y, af[i].z, af[i].w, bf[1].z, bf[1].w);
            }
        }
        st = (st + 1 == GSTAGES) ? 0 : st + 1;
    }

#pragma unroll
    for (int i = 0; i < 2; i++) {
#pragma unroll
        for (int j = 0; j < 4; j++) {
            long row = rowBase + warpM * 32 + i * 16 + grp;
            int col = colBase + warpN * 32 + j * 8 + tig * 2;
#pragma unroll
            for (int half_ = 0; half_ < 2; half_++) {
                long r = row + half_ * 8;
                float v0 = acc[i][j][half_ * 2];
                float v1 = acc[i][j][half_ * 2 + 1];
                int bb = (int)(r >> 11);
                if (mode == 2) {
                    v0 = EX[r * ldc + col] + ada[bb * 6 * D_ + adaOff + col] * v0;
                    v1 = EX[r * ldc + col + 1] + ada[bb * 6 * D_ + adaOff + col + 1] * v1;
                } else {  // mode 3
                    v0 = EX[r * ldc + col] + ada[bb * 6 * D_ + adaOff + col] * (v0 + evec[col]);
                    v1 = EX[r * ldc + col + 1] + ada[bb * 6 * D_ + adaOff + col + 1] * (v1 + evec[col + 1]);
                }
                *reinterpret_cast<float2*>(&Cf[r * ldc + col]) = make_float2(v0, v1);
            }
        }
    }
}

// ---------------- adaLN ----------------
__global__ void __launch_bounds__(256) ada_kernel(
    const float* __restrict__ c, const float* __restrict__ w,
    const float* __restrict__ bias, float* __restrict__ out)
{
    int warp = (blockIdx.x * blockDim.x + threadIdx.x) >> 5;
    int lane = threadIdx.x & 31;
    if (warp >= 6 * D_) return;
    const float* wr = w + (long)warp * D_;
    float s0 = 0.f, s1 = 0.f;
    for (int d = lane; d < D_; d += 32) {
        float wv = wr[d];
        s0 += c[d] * wv;
        s1 += c[D_ + d] * wv;
    }
#pragma unroll
    for (int o = 16; o > 0; o >>= 1) {
        s0 += __shfl_down_sync(0xffffffffu, s0, o);
        s1 += __shfl_down_sync(0xffffffffu, s1, o);
    }
    if (lane == 0) {
        out[warp] = s0 + bias[warp];
        out[6 * D_ + warp] = s1 + bias[warp];
    }
}

// ---------------- LayerNorm + modulate, fp16 output ----------------
__global__ void __launch_bounds__(256) ln_mod_kernel(
    const float* __restrict__ x, const float* __restrict__ w,
    const float* __restrict__ ada, int shOff, int scOff, __half* __restrict__ h)
{
    int r = blockIdx.x;
    int b = r >> 11;
    const float* xr = x + (long)r * D_;
    int tid = threadIdx.x;
    float s = 0.f, ss = 0.f;
    float vals[4];
#pragma unroll
    for (int i = 0; i < 4; i++) {
        float v = xr[tid + i * 256];
        vals[i] = v; s += v; ss += v * v;
    }
    __shared__ float rs[256], rss[256];
    rs[tid] = s; rss[tid] = ss;
    __syncthreads();
    for (int st = 128; st > 0; st >>= 1) {
        if (tid < st) { rs[tid] += rs[tid + st]; rss[tid] += rss[tid + st]; }
        __syncthreads();
    }
    float mean = rs[0] * (1.f / D_);
    float var = rss[0] * (1.f / D_) - mean * mean;
    float inv = rsqrtf(var + 1e-5f);
    const float* sh = ada + b * 6 * D_ + shOff;
    const float* sc = ada + b * 6 * D_ + scOff;
#pragma unroll
    for (int i = 0; i < 4; i++) {
        int d = tid + i * 256;
        h[(long)r * D_ + d] =
            __float2half_rn((vals[i] - mean) * inv * w[d] * (1.f + sc[d]) + sh[d]);
    }
}

// ---------------- launch ----------------
extern "C" void kernel_launch(void* const* d_in, const int* in_sizes, int n_in,
                              void* d_out, int out_size)
{
    (void)in_sizes; (void)n_in; (void)out_size;
    const float* x       = (const float*)d_in[0];
    const float* c       = (const float*)d_in[3];
    const float* norm1_w = (const float*)d_in[4];
    const float* w_qkv   = (const float*)d_in[5];
    const float* w_out   = (const float*)d_in[6];
    const float* norm2_w = (const float*)d_in[7];
    const float* mlp_w1  = (const float*)d_in[8];
    const float* mlp_b1  = (const float*)d_in[9];
    const float* mlp_w2  = (const float*)d_in[10];
    const float* mlp_b2  = (const float*)d_in[11];
    const float* ada_w   = (const float*)d_in[12];
    const float* ada_b   = (const float*)d_in[13];
    float* out = (float*)d_out;

    float *ada, *x1;
    __half *h, *qkh, *vt, *attn2, *mlp, *wqkv_h, *wout_h, *w1_h, *w2_h;
    cudaGetSymbolAddress((void**)&ada,    g_ada);
    cudaGetSymbolAddress((void**)&h,      g_h);
    cudaGetSymbolAddress((void**)&qkh,    g_qkh);
    cudaGetSymbolAddress((void**)&vt,     g_vt);
    cudaGetSymbolAddress((void**)&attn2,  g_attn2);
    cudaGetSymbolAddress((void**)&x1,     g_x1);
    cudaGetSymbolAddress((void**)&mlp,    g_mlp);
    cudaGetSymbolAddress((void**)&wqkv_h, g_wqkv);
    cudaGetSymbolAddress((void**)&wout_h, g_wout);
    cudaGetSymbolAddress((void**)&w1_h,   g_w1);
    cudaGetSymbolAddress((void**)&w2_h,   g_w2);

    static int inited = 0;
    if (!inited) {
        cudaFuncSetAttribute(flash_attn, cudaFuncAttributeMaxDynamicSharedMemorySize, FA_SMEM);
        cudaFuncSetAttribute(gemm_nt_f16, cudaFuncAttributeMaxDynamicSharedMemorySize, GEMM_SMEM);
        cudaFuncSetAttribute(gemm_nt_f16_m64, cudaFuncAttributeMaxDynamicSharedMemorySize, GEMM64_SMEM);
        inited = 1;
    }

    // 0. convert weights to fp16
    conv_all<<<12 * D_ * D_ / 4 / 256, 256>>>(w_qkv, w_out, mlp_w1, mlp_w2,
                                              wqkv_h, wout_h, w1_h, w2_h);
    // 1. adaLN projection
    ada_kernel<<<768, 256>>>(c, ada_w, ada_b, ada);
    // 2. LN1 + modulate -> fp16 h
    ln_mod_kernel<<<B_ * S_, 256>>>(x, norm1_w, ada, 0, D_, h);
    // 3. QKV GEMM -> Q(x log2e/8),K fp16 + V^T fp16
    gemm_nt_f16<<<dim3(24, 32), 256, GEMM_SMEM>>>(h, wqkv_h, nullptr, D_,
                                                  D_, D_, 0, 4,
                                                  nullptr, nullptr, nullptr, 0,
                                                  qkh, vt);
    // 4. flash attention -> attn2 fp16
    flash_attn<<<dim3(S_ / 128, B_ * H_), 256, FA_SMEM>>>(qkh, vt, attn2);
    // 5. out-proj + residual1 (64-row tiles for wave fill)
    gemm_nt_f16_m64<<<dim3(8, 64), 256, GEMM64_SMEM>>>(attn2, wout_h, x1, D_,
                                                       D_, D_, D_, 2,
                                                       x, nullptr, ada, 2 * D_);
    // 6. LN2 + modulate -> fp16 h
    ln_mod_kernel<<<B_ * S_, 256>>>(x1, norm2_w, ada, 3 * D_, 4 * D_, h);
    // 7. MLP1 + bias + gelu -> fp16 mlp
    gemm_nt_f16<<<dim3(32, 32), 256, GEMM_SMEM>>>(h, w1_h, mlp, D_,
                                                  D_, D_, 4 * D_, 1,
                                                  nullptr, mlp_b1, nullptr, 0,
                                                  nullptr, nullptr);
    // 8. MLP2 + final residual (64-row tiles for wave fill)
    gemm_nt_f16_m64<<<dim3(8, 64), 256, GEMM64_SMEM>>>(mlp, w2_h, out, 4 * D_,
                                                       4 * D_, 4 * D_, D_, 3,
                                                       x1, mlp_b2, ada, 5 * D_);
}

// round 15
// speedup vs baseline: 1.1124x; 1.1124x over previous
#include <cuda_runtime.h>
#include <cuda_fp16.h>
#include <math.h>

#define B_ 2
#define S_ 2048
#define D_ 1024
#define H_ 16
#define HD_ 64

// ---------------- scratch ----------------
__device__ float  g_ada[B_ * 6 * D_];
__device__ __half g_h[(size_t)B_ * S_ * D_];
__device__ __half g_qkh[(size_t)B_ * S_ * 2 * D_];           // Q(scaled by log2e/8),K fp16
__device__ __half g_vt[(size_t)B_ * H_ * HD_ * S_];          // V^T fp16
__device__ __half g_attn2[(size_t)B_ * S_ * D_];
__device__ float  g_x1[(size_t)B_ * S_ * D_];
__device__ __half g_mlp[(size_t)B_ * S_ * 4 * D_];
__device__ __half g_wqkv[(size_t)3 * D_ * D_];
__device__ __half g_wout[(size_t)D_ * D_];
__device__ __half g_w1[(size_t)4 * D_ * D_];
__device__ __half g_w2[(size_t)4 * D_ * D_];

__device__ __forceinline__ float gelu_tanh(float v) {
    float u = 0.7978845608028654f * (v + 0.044715f * v * v * v);
    return 0.5f * v * (1.f + tanhf(u));
}

__device__ __forceinline__ void cp16(void* s, const void* g) {
    unsigned sa = (unsigned)__cvta_generic_to_shared(s);
    asm volatile("cp.async.cg.shared.global [%0], [%1], 16;" :: "r"(sa), "l"(g));
}
#define CP_COMMIT() asm volatile("cp.async.commit_group;")
#define CP_WAIT(n)  asm volatile("cp.async.wait_group %0;" :: "n"(n))

#define MMA16(d0,d1,d2,d3,a0,a1,a2,a3,b0,b1) \
    asm volatile( \
        "mma.sync.aligned.m16n8k16.row.col.f32.f16.f16.f32 " \
        "{%0,%1,%2,%3}, {%4,%5,%6,%7}, {%8,%9}, {%0,%1,%2,%3};" \
        : "+f"(d0), "+f"(d1), "+f"(d2), "+f"(d3) \
        : "r"(a0), "r"(a1), "r"(a2), "r"(a3), "r"(b0), "r"(b1))

__device__ __forceinline__ uint4 ldsm4(const __half* p) {
    uint4 r;
    unsigned a = (unsigned)__cvta_generic_to_shared(p);
    asm volatile("ldmatrix.sync.aligned.m8n8.x4.shared.b16 {%0,%1,%2,%3}, [%4];"
                 : "=r"(r.x), "=r"(r.y), "=r"(r.z), "=r"(r.w) : "r"(a));
    return r;
}

__device__ __forceinline__ unsigned pack_h2(float a, float b) {
    __half2 h = __floats2half2_rn(a, b);
    return *reinterpret_cast<unsigned*>(&h);
}

// ---------------- convert all weights fp32 -> fp16 (one launch) ----------------
__global__ void conv_all(const float* __restrict__ wq, const float* __restrict__ wo,
                         const float* __restrict__ w1, const float* __restrict__ w2,
                         __half* __restrict__ oq, __half* __restrict__ oo,
                         __half* __restrict__ o1, __half* __restrict__ o2)
{
    const long n_q = 3L * D_ * D_ / 4, n_o = (long)D_ * D_ / 4, n_m = (long)D_ * D_;
    long i = (long)blockIdx.x * 256 + threadIdx.x;
    const float* src; __half* dst; long off;
    if (i < n_q)                  { src = wq; dst = oq; off = i; }
    else if (i < n_q + n_o)       { src = wo; dst = oo; off = i - n_q; }
    else if (i < n_q + n_o + n_m) { src = w1; dst = o1; off = i - n_q - n_o; }
    else                          { src = w2; dst = o2; off = i - n_q - n_o - n_m; }
    float4 v = reinterpret_cast<const float4*>(src)[off];
    reinterpret_cast<__half2*>(dst)[off * 2]     = __floats2half2_rn(v.x, v.y);
    reinterpret_cast<__half2*>(dst)[off * 2 + 1] = __floats2half2_rn(v.z, v.w);
}

// ============================================================================
// Fused flash attention, fp16 mma + ldmatrix, base-2 softmax.
// P kept entirely in registers (QK C-fragment == PV A-fragment layout).
// Q tile 128 rows, 256 threads = 8 warps, 2 CTAs/SM.
// smem: Q[128][72] + K 2x[64][72] + V 2x[64][72] = 27648 halves = 55296 B
// ============================================================================
#define FA_SMEM 55296

__global__ void __launch_bounds__(256, 2) flash_attn(
    const __half* __restrict__ qkh, const __half* __restrict__ vt,
    __half* __restrict__ out)
{
    extern __shared__ __half sm[];
    __half* Qs = sm;                        // [128][72]
    __half* Ks = sm + 9216;                 // [2][64][72]
    __half* Vs = sm + 18432;                // [2][64][72]

    const int tid  = threadIdx.x;
    const int lane = tid & 31;
    const int warp = tid >> 5;
    const int grp  = lane >> 2;
    const int tig  = lane & 3;
    const int b    = blockIdx.y >> 4;
    const int h    = blockIdx.y & 15;
    const int qBase = blockIdx.x * 128;

    const int rA = (lane & 7) + ((lane >> 3) & 1) * 8;
    const int cA = ((lane >> 4) & 1) * 8;
    const int rB = (lane & 7) + ((lane >> 4) & 1) * 8;
    const int cB = ((lane >> 3) & 1) * 8;

    const __half* vth = vt + ((long)(b * H_ + h) * HD_) * S_;

    // ---- prologue ----
#pragma unroll
    for (int i = 0; i < 4; i++) {
        int idx = tid + i * 256;
        int r   = idx >> 3;
        int q8  = idx & 7;
        cp16(&Qs[r * 72 + q8 * 8],
             &qkh[((long)(b * S_ + qBase + r)) * 2048 + h * 64 + q8 * 8]);
    }
#pragma unroll
    for (int i = 0; i < 2; i++) {
        int idx = tid + i * 256;
        int r   = idx >> 3;
        int q8  = idx & 7;
        cp16(&Ks[r * 72 + q8 * 8],
             &qkh[((long)(b * S_ + r)) * 2048 + 1024 + h * 64 + q8 * 8]);
        cp16(&Vs[r * 72 + q8 * 8], &vth[(long)r * S_ + q8 * 8]);
    }
    CP_COMMIT();

    const __half* Qw = Qs + warp * 16 * 72;

    float m0 = -INFINITY, m1 = -INFINITY, l0 = 0.f, l1 = 0.f;
    float o[8][4];
#pragma unroll
    for (int j = 0; j < 8; j++)
#pragma unroll
        for (int t = 0; t < 4; t++) o[j][t] = 0.f;

    const int nT = S_ / 64;
    for (int t = 0; t < nT; t++) {
        CP_WAIT(0);
        __syncthreads();

        if (t + 1 < nT) {
            __half* Kn = Ks + ((t + 1) & 1) * 4608;
            __half* Vn = Vs + ((t + 1) & 1) * 4608;
            int kt = (t + 1) * 64;
#pragma unroll
            for (int i = 0; i < 2; i++) {
                int idx = tid + i * 256;
                int r   = idx >> 3;
                int q8  = idx & 7;
                cp16(&Kn[r * 72 + q8 * 8],
                     &qkh[((long)(b * S_ + kt + r)) * 2048 + 1024 + h * 64 + q8 * 8]);
                cp16(&Vn[r * 72 + q8 * 8], &vth[(long)r * S_ + kt + q8 * 8]);
            }
        }
        CP_COMMIT();

        const __half* Kc = Ks + (t & 1) * 4608;
        const __half* Vc = Vs + (t & 1) * 4608;

        // ---- scores = Q @ K^T (log2 domain) ----
        float s[8][4];
#pragma unroll
        for (int j = 0; j < 8; j++)
#pragma unroll
            for (int tt = 0; tt < 4; tt++) s[j][tt] = 0.f;

#pragma unroll
        for (int kk = 0; kk < 64; kk += 16) {
            uint4 aq = ldsm4(&Qw[rA * 72 + kk + cA]);
#pragma unroll
            for (int jp = 0; jp < 4; jp++) {
                uint4 bk = ldsm4(&Kc[(jp * 16 + rB) * 72 + kk + cB]);
                MMA16(s[2*jp][0],   s[2*jp][1],   s[2*jp][2],   s[2*jp][3],
                      aq.x, aq.y, aq.z, aq.w, bk.x, bk.y);
                MMA16(s[2*jp+1][0], s[2*jp+1][1], s[2*jp+1][2], s[2*jp+1][3],
                      aq.x, aq.y, aq.z, aq.w, bk.z, bk.w);
            }
        }

        // ---- online softmax (base 2), P packed directly into A-fragments ----
        float mx0 = -INFINITY, mx1 = -INFINITY;
#pragma unroll
        for (int j = 0; j < 8; j++) {
            mx0 = fmaxf(mx0, fmaxf(s[j][0], s[j][1]));
            mx1 = fmaxf(mx1, fmaxf(s[j][2], s[j][3]));
        }
        mx0 = fmaxf(mx0, __shfl_xor_sync(0xffffffffu, mx0, 1));
        mx0 = fmaxf(mx0, __shfl_xor_sync(0xffffffffu, mx0, 2));
        mx1 = fmaxf(mx1, __shfl_xor_sync(0xffffffffu, mx1, 1));
        mx1 = fmaxf(mx1, __shfl_xor_sync(0xffffffffu, mx1, 2));
        float mn0 = fmaxf(m0, mx0), mn1 = fmaxf(m1, mx1);
        float sc0 = exp2f(m0 - mn0), sc1 = exp2f(m1 - mn1);

        unsigned pr0[8], pr1[8];            // half2: rows grp / grp+8
        float sum0 = 0.f, sum1 = 0.f;
#pragma unroll
        for (int j = 0; j < 8; j++) {
            float p0 = exp2f(s[j][0] - mn0);
            float p1 = exp2f(s[j][1] - mn0);
            float p2 = exp2f(s[j][2] - mn1);
            float p3 = exp2f(s[j][3] - mn1);
            sum0 += p0 + p1; sum1 += p2 + p3;
            pr0[j] = pack_h2(p0, p1);
            pr1[j] = pack_h2(p2, p3);
        }
        sum0 += __shfl_xor_sync(0xffffffffu, sum0, 1);
        sum0 += __shfl_xor_sync(0xffffffffu, sum0, 2);
        sum1 += __shfl_xor_sync(0xffffffffu, sum1, 1);
        sum1 += __shfl_xor_sync(0xffffffffu, sum1, 2);
        l0 = l0 * sc0 + sum0;
        l1 = l1 * sc1 + sum1;
        m0 = mn0; m1 = mn1;

#pragma unroll
        for (int j = 0; j < 8; j++) {
            o[j][0] *= sc0; o[j][1] *= sc0;
            o[j][2] *= sc1; o[j][3] *= sc1;
        }

        // ---- O += P @ V  (A-fragments straight from registers) ----
#pragma unroll
        for (int kk = 0; kk < 64; kk += 16) {
            unsigned a0 = pr0[kk >> 3];
            unsigned a1 = pr1[kk >> 3];
            unsigned a2 = pr0[(kk >> 3) + 1];
            unsigned a3 = pr1[(kk >> 3) + 1];
#pragma unroll
            for (int jp = 0; jp < 4; jp++) {
                uint4 bv = ldsm4(&Vc[(jp * 16 + rB) * 72 + kk + cB]);
                MMA16(o[2*jp][0],   o[2*jp][1],   o[2*jp][2],   o[2*jp][3],
                      a0, a1, a2, a3, bv.x, bv.y);
                MMA16(o[2*jp+1][0], o[2*jp+1][1], o[2*jp+1][2], o[2*jp+1][3],
                      a0, a1, a2, a3, bv.z, bv.w);
            }
        }
    }

    float inv0 = 1.f / l0, inv1 = 1.f / l1;
    int row0 = qBase + warp * 16 + grp;
#pragma unroll
    for (int j = 0; j < 8; j++) {
        int col = h * 64 + j * 8 + tig * 2;
        *reinterpret_cast<__half2*>(&out[((long)(b * S_ + row0)) * D_ + col]) =
            __floats2half2_rn(o[j][0] * inv0, o[j][1] * inv0);
        *reinterpret_cast<__half2*>(&out[((long)(b * S_ + row0 + 8)) * D_ + col]) =
            __floats2half2_rn(o[j][2] * inv1, o[j][3] * inv1);
    }
}

// ============================================================================
// FP16 NT GEMM (m16n8k16), 4-stage cp.async, ldmatrix, 2 CTAs/SM. (R12 champion)
// mode 4: qkv split (Q scaled log2e/8); mode 1: gelu->half;
// mode 2: EX+ada*v; mode 3: EX+ada*(v+evec)
// ============================================================================
#define GSTAGES 4
#define GEMM_SMEM (GSTAGES * 128 * 40 * 2 * 2)   // 81920 B

__global__ void __launch_bounds__(256, 2) gemm_nt_f16(
    const __half* __restrict__ A, const __half* __restrict__ B, void* __restrict__ Cv,
    int K, int lda, int ldb, int ldc,
    int mode, const float* __restrict__ EX, const float* __restrict__ evec,
    const float* __restrict__ ada, int adaOff,
    __half* __restrict__ qh, __half* __restrict__ vth)
{
    extern __shared__ __half hsm[];
    __half* Asm = hsm;
    __half* Bsm = hsm + GSTAGES * 128 * 40;

    const int tid   = threadIdx.x;
    const int lane  = tid & 31;
    const int warp  = tid >> 5;
    const int warpM = warp & 1;
    const int warpN = warp >> 1;
    const int grp   = lane >> 2;
    const int tig   = lane & 3;

    const int rowBase = blockIdx.y * 128;
    const int colBase = blockIdx.x * 128;

    const int rA = (lane & 7) + ((lane >> 3) & 1) * 8;
    const int cA = ((lane >> 4) & 1) * 8;
    const int rB = (lane & 7) + ((lane >> 4) & 1) * 8;
    const int cB = ((lane >> 3) & 1) * 8;

    float acc[4][4][4];
#pragma unroll
    for (int i = 0; i < 4; i++)
#pragma unroll
        for (int j = 0; j < 4; j++)
#pragma unroll
            for (int t = 0; t < 4; t++) acc[i][j][t] = 0.f;

    const int nCh = K >> 5;

    auto load_chunk = [&](int c, int st) {
        __half* as = Asm + st * 128 * 40;
        __half* bs = Bsm + st * 128 * 40;
#pragma unroll
        for (int it = 0; it < 2; it++) {
            int s = tid + it * 256;
            int r = s >> 2;
            int q = s & 3;
            cp16(&as[r * 40 + q * 8], A + (long)(rowBase + r) * lda + c * 32 + q * 8);
            cp16(&bs[r * 40 + q * 8], B + (long)(colBase + r) * ldb + c * 32 + q * 8);
        }
    };

#pragma unroll
    for (int s = 0; s < GSTAGES - 1; s++) {
        if (s < nCh) load_chunk(s, s);
        CP_COMMIT();
    }

    int st = 0;
    for (int c = 0; c < nCh; c++) {
        CP_WAIT(GSTAGES - 2);
        __syncthreads();

        int nc = c + GSTAGES - 1;
        if (nc < nCh) load_chunk(nc, nc % GSTAGES);
        CP_COMMIT();

        const __half* as = Asm + st * 128 * 40;
        const __half* bs = Bsm + st * 128 * 40;
#pragma unroll
        for (int kb = 0; kb < 2; kb++) {
            const int kk = kb * 16;
            uint4 af[4], bf[2];
#pragma unroll
            for (int i = 0; i < 4; i++)
                af[i] = ldsm4(&as[(warpM * 64 + i * 16 + rA) * 40 + kk + cA]);
#pragma unroll
            for (int jp = 0; jp < 2; jp++)
                bf[jp] = ldsm4(&bs[(warpN * 32 + jp * 16 + rB) * 40 + kk + cB]);
#pragma unroll
            for (int i = 0; i < 4; i++) {
                MMA16(acc[i][0][0], acc[i][0][1], acc[i][0][2], acc[i][0][3],
                      af[i].x, af[i].y, af[i].z, af[i].w, bf[0].x, bf[0].y);
                MMA16(acc[i][1][0], acc[i][1][1], acc[i][1][2], acc[i][1][3],
                      af[i].x, af[i].y, af[i].z, af[i].w, bf[0].z, bf[0].w);
                MMA16(acc[i][2][0], acc[i][2][1], acc[i][2][2], acc[i][2][3],
                      af[i].x, af[i].y, af[i].z, af[i].w, bf[1].x, bf[1].y);
                MMA16(acc[i][3][0], acc[i][3][1], acc[i][3][2], acc[i][3][3],
                      af[i].x, af[i].y, af[i].z, af[i].w, bf[1].z, bf[1].w);
            }
        }
        st = (st + 1 == GSTAGES) ? 0 : st + 1;
    }

    // ---- epilogue ----
    float* Cf = (float*)Cv;
    __half* Ch = (__half*)Cv;
#pragma unroll
    for (int i = 0; i < 4; i++) {
#pragma unroll
        for (int j = 0; j < 4; j++) {
            long row = rowBase + warpM * 64 + i * 16 + grp;
            int col = colBase + warpN * 32 + j * 8 + tig * 2;
#pragma unroll
            for (int half_ = 0; half_ < 2; half_++) {
                long r = row + half_ * 8;
                float v0 = acc[i][j][half_ * 2];
                float v1 = acc[i][j][half_ * 2 + 1];
                if (mode == 4) {
                    if (col < 2048) {
                        float qs = (col < 1024) ? 0.18033688011112042f : 1.f;
                        *reinterpret_cast<__half2*>(&qh[r * 2048 + col]) =
                            __floats2half2_rn(v0 * qs, v1 * qs);
                    } else {
                        int hh = (col - 2048) >> 6;
                        int hd = (col - 2048) & 63;
                        int bb = (int)(r >> 11), ss = (int)(r & 2047);
                        __half* base = vth + (((long)(bb * H_ + hh) * HD_ + hd)) * S_ + ss;
                        base[0]  = __float2half_rn(v0);
                        base[S_] = __float2half_rn(v1);
                    }
                } else if (mode == 1) {
                    *reinterpret_cast<__half2*>(&Ch[r * ldc + col]) =
                        __floats2half2_rn(gelu_tanh(v0 + evec[col]),
                                          gelu_tanh(v1 + evec[col + 1]));
                } else if (mode == 2) {
                    int bb = (int)(r >> 11);
                    v0 = EX[r * ldc + col] + ada[bb * 6 * D_ + adaOff + col] * v0;
                    v1 = EX[r * ldc + col + 1] + ada[bb * 6 * D_ + adaOff + col + 1] * v1;
                    *reinterpret_cast<float2*>(&Cf[r * ldc + col]) = make_float2(v0, v1);
                } else {  // mode 3
                    int bb = (int)(r >> 11);
                    v0 = EX[r * ldc + col] + ada[bb * 6 * D_ + adaOff + col] * (v0 + evec[col]);
                    v1 = EX[r * ldc + col + 1] + ada[bb * 6 * D_ + adaOff + col + 1] * (v1 + evec[col + 1]);
                    *reinterpret_cast<float2*>(&Cf[r * ldc + col]) = make_float2(v0, v1);
                }
            }
        }
    }
}

// ---------------- adaLN ----------------
__global__ void __launch_bounds__(256) ada_kernel(
    const float* __restrict__ c, const float* __restrict__ w,
    const float* __restrict__ bias, float* __restrict__ out)
{
    int warp = (blockIdx.x * blockDim.x + threadIdx.x) >> 5;
    int lane = threadIdx.x & 31;
    if (warp >= 6 * D_) return;
    const float* wr = w + (long)warp * D_;
    float s0 = 0.f, s1 = 0.f;
    for (int d = lane; d < D_; d += 32) {
        float wv = wr[d];
        s0 += c[d] * wv;
        s1 += c[D_ + d] * wv;
    }
#pragma unroll
    for (int o = 16; o > 0; o >>= 1) {
        s0 += __shfl_down_sync(0xffffffffu, s0, o);
        s1 += __shfl_down_sync(0xffffffffu, s1, o);
    }
    if (lane == 0) {
        out[warp] = s0 + bias[warp];
        out[6 * D_ + warp] = s1 + bias[warp];
    }
}

// ---------------- LayerNorm + modulate, fp16 output ----------------
__global__ void __launch_bounds__(256) ln_mod_kernel(
    const float* __restrict__ x, const float* __restrict__ w,
    const float* __restrict__ ada, int shOff, int scOff, __half* __restrict__ h)
{
    int r = blockIdx.x;
    int b = r >> 11;
    const float* xr = x + (long)r * D_;
    int tid = threadIdx.x;
    float s = 0.f, ss = 0.f;
    float vals[4];
#pragma unroll
    for (int i = 0; i < 4; i++) {
        float v = xr[tid + i * 256];
        vals[i] = v; s += v; ss += v * v;
    }
    __shared__ float rs[256], rss[256];
    rs[tid] = s; rss[tid] = ss;
    __syncthreads();
    for (int st = 128; st > 0; st >>= 1) {
        if (tid < st) { rs[tid] += rs[tid + st]; rss[tid] += rss[tid + st]; }
        __syncthreads();
    }
    float mean = rs[0] * (1.f / D_);
    float var = rss[0] * (1.f / D_) - mean * mean;
    float inv = rsqrtf(var + 1e-5f);
    const float* sh = ada + b * 6 * D_ + shOff;
    const float* sc = ada + b * 6 * D_ + scOff;
#pragma unroll
    for (int i = 0; i < 4; i++) {
        int d = tid + i * 256;
        h[(long)r * D_ + d] =
            __float2half_rn((vals[i] - mean) * inv * w[d] * (1.f + sc[d]) + sh[d]);
    }
}

// ---------------- launch ----------------
extern "C" void kernel_launch(void* const* d_in, const int* in_sizes, int n_in,
                              void* d_out, int out_size)
{
    (void)in_sizes; (void)n_in; (void)out_size;
    const float* x       = (const float*)d_in[0];
    const float* c       = (const float*)d_in[3];
    const float* norm1_w = (const float*)d_in[4];
    const float* w_qkv   = (const float*)d_in[5];
    const float* w_out   = (const float*)d_in[6];
    const float* norm2_w = (const float*)d_in[7];
    const float* mlp_w1  = (const float*)d_in[8];
    const float* mlp_b1  = (const float*)d_in[9];
    const float* mlp_w2  = (const float*)d_in[10];
    const float* mlp_b2  = (const float*)d_in[11];
    const float* ada_w   = (const float*)d_in[12];
    const float* ada_b   = (const float*)d_in[13];
    float* out = (float*)d_out;

    float *ada, *x1;
    __half *h, *qkh, *vt, *attn2, *mlp, *wqkv_h, *wout_h, *w1_h, *w2_h;
    cudaGetSymbolAddress((void**)&ada,    g_ada);
    cudaGetSymbolAddress((void**)&h,      g_h);
    cudaGetSymbolAddress((void**)&qkh,    g_qkh);
    cudaGetSymbolAddress((void**)&vt,     g_vt);
    cudaGetSymbolAddress((void**)&attn2,  g_attn2);
    cudaGetSymbolAddress((void**)&x1,     g_x1);
    cudaGetSymbolAddress((void**)&mlp,    g_mlp);
    cudaGetSymbolAddress((void**)&wqkv_h, g_wqkv);
    cudaGetSymbolAddress((void**)&wout_h, g_wout);
    cudaGetSymbolAddress((void**)&w1_h,   g_w1);
    cudaGetSymbolAddress((void**)&w2_h,   g_w2);

    static int inited = 0;
    if (!inited) {
        cudaFuncSetAttribute(flash_attn, cudaFuncAttributeMaxDynamicSharedMemorySize, FA_SMEM);
        cudaFuncSetAttribute(gemm_nt_f16, cudaFuncAttributeMaxDynamicSharedMemorySize, GEMM_SMEM);
        inited = 1;
    }

    // 0. convert weights to fp16
    conv_all<<<12 * D_ * D_ / 4 / 256, 256>>>(w_qkv, w_out, mlp_w1, mlp_w2,
                                              wqkv_h, wout_h, w1_h, w2_h);
    // 1. adaLN projection
    ada_kernel<<<768, 256>>>(c, ada_w, ada_b, ada);
    // 2. LN1 + modulate -> fp16 h
    ln_mod_kernel<<<B_ * S_, 256>>>(x, norm1_w, ada, 0, D_, h);
    // 3. QKV GEMM -> Q(x log2e/8),K fp16 + V^T fp16
    gemm_nt_f16<<<dim3(24, 32), 256, GEMM_SMEM>>>(h, wqkv_h, nullptr, D_,
                                                  D_, D_, 0, 4,
                                                  nullptr, nullptr, nullptr, 0,
                                                  qkh, vt);
    // 4. flash attention (P in registers) -> attn2 fp16
    flash_attn<<<dim3(S_ / 128, B_ * H_), 256, FA_SMEM>>>(qkh, vt, attn2);
    // 5. out-proj + residual1 (fp32 out)
    gemm_nt_f16<<<dim3(8, 32), 256, GEMM_SMEM>>>(attn2, wout_h, x1, D_,
                                                 D_, D_, D_, 2,
                                                 x, nullptr, ada, 2 * D_,
                                                 nullptr, nullptr);
    // 6. LN2 + modulate -> fp16 h
    ln_mod_kernel<<<B_ * S_, 256>>>(x1, norm2_w, ada, 3 * D_, 4 * D_, h);
    // 7. MLP1 + bias + gelu -> fp16 mlp
    gemm_nt_f16<<<dim3(32, 32), 256, GEMM_SMEM>>>(h, w1_h, mlp, D_,
                                                  D_, D_, 4 * D_, 1,
                                                  nullptr, mlp_b1, nullptr, 0,
                                                  nullptr, nullptr);
    // 8. MLP2 + final residual (fp32 out)
    gemm_nt_f16<<<dim3(8, 32), 256, GEMM_SMEM>>>(mlp, w2_h, out, 4 * D_,
                                                 4 * D_, 4 * D_, D_, 3,
                                                 x1, mlp_b2, ada, 5 * D_,
                                                 nullptr, nullptr);
}

// round 16
// speedup vs baseline: 1.1427x; 1.0272x over previous
#include <cuda_runtime.h>
#include <cuda_fp16.h>
#include <math.h>

#define B_ 2
#define S_ 2048
#define D_ 1024
#define H_ 16
#define HD_ 64

// ---------------- scratch ----------------
__device__ float  g_ada[B_ * 6 * D_];
__device__ __half g_h[(size_t)B_ * S_ * D_];
__device__ __half g_qkh[(size_t)B_ * S_ * 2 * D_];           // Q(scaled by log2e/8),K fp16
__device__ __half g_vt[(size_t)B_ * H_ * HD_ * S_];          // V^T fp16
__device__ __half g_attn2[(size_t)B_ * S_ * D_];
__device__ float  g_x1[(size_t)B_ * S_ * D_];
__device__ __half g_mlp[(size_t)B_ * S_ * 4 * D_];
__device__ __half g_wqkv[(size_t)3 * D_ * D_];
__device__ __half g_wout[(size_t)D_ * D_];
__device__ __half g_w1[(size_t)4 * D_ * D_];
__device__ __half g_w2[(size_t)4 * D_ * D_];

__device__ __forceinline__ float tanh_fast(float x) {
    float y;
    asm("tanh.approx.f32 %0, %1;" : "=f"(y) : "f"(x));
    return y;
}

__device__ __forceinline__ float gelu_tanh(float v) {
    float u = 0.7978845608028654f * (v + 0.044715f * v * v * v);
    return 0.5f * v * (1.f + tanh_fast(u));
}

__device__ __forceinline__ void cp16(void* s, const void* g) {
    unsigned sa = (unsigned)__cvta_generic_to_shared(s);
    asm volatile("cp.async.cg.shared.global [%0], [%1], 16;" :: "r"(sa), "l"(g));
}
#define CP_COMMIT() asm volatile("cp.async.commit_group;")
#define CP_WAIT(n)  asm volatile("cp.async.wait_group %0;" :: "n"(n))

#define MMA16(d0,d1,d2,d3,a0,a1,a2,a3,b0,b1) \
    asm volatile( \
        "mma.sync.aligned.m16n8k16.row.col.f32.f16.f16.f32 " \
        "{%0,%1,%2,%3}, {%4,%5,%6,%7}, {%8,%9}, {%0,%1,%2,%3};" \
        : "+f"(d0), "+f"(d1), "+f"(d2), "+f"(d3) \
        : "r"(a0), "r"(a1), "r"(a2), "r"(a3), "r"(b0), "r"(b1))

__device__ __forceinline__ uint4 ldsm4(const __half* p) {
    uint4 r;
    unsigned a = (unsigned)__cvta_generic_to_shared(p);
    asm volatile("ldmatrix.sync.aligned.m8n8.x4.shared.b16 {%0,%1,%2,%3}, [%4];"
                 : "=r"(r.x), "=r"(r.y), "=r"(r.z), "=r"(r.w) : "r"(a));
    return r;
}

__device__ __forceinline__ unsigned pack_h2(float a, float b) {
    __half2 h = __floats2half2_rn(a, b);
    return *reinterpret_cast<unsigned*>(&h);
}

// ---------------- convert all weights fp32 -> fp16 (one launch) ----------------
__global__ void conv_all(const float* __restrict__ wq, const float* __restrict__ wo,
                         const float* __restrict__ w1, const float* __restrict__ w2,
                         __half* __restrict__ oq, __half* __restrict__ oo,
                         __half* __restrict__ o1, __half* __restrict__ o2)
{
    const long n_q = 3L * D_ * D_ / 4, n_o = (long)D_ * D_ / 4, n_m = (long)D_ * D_;
    long i = (long)blockIdx.x * 256 + threadIdx.x;
    const float* src; __half* dst; long off;
    if (i < n_q)                  { src = wq; dst = oq; off = i; }
    else if (i < n_q + n_o)       { src = wo; dst = oo; off = i - n_q; }
    else if (i < n_q + n_o + n_m) { src = w1; dst = o1; off = i - n_q - n_o; }
    else                          { src = w2; dst = o2; off = i - n_q - n_o - n_m; }
    float4 v = reinterpret_cast<const float4*>(src)[off];
    reinterpret_cast<__half2*>(dst)[off * 2]     = __floats2half2_rn(v.x, v.y);
    reinterpret_cast<__half2*>(dst)[off * 2 + 1] = __floats2half2_rn(v.z, v.w);
}

// ============================================================================
// Fused flash attention, fp16 mma + ldmatrix, base-2 softmax, P in registers.
// Q tile 128 rows, 256 threads = 8 warps, 2 CTAs/SM.
// ============================================================================
#define FA_SMEM 55296

__global__ void __launch_bounds__(256, 2) flash_attn(
    const __half* __restrict__ qkh, const __half* __restrict__ vt,
    __half* __restrict__ out)
{
    extern __shared__ __half sm[];
    __half* Qs = sm;                        // [128][72]
    __half* Ks = sm + 9216;                 // [2][64][72]
    __half* Vs = sm + 18432;                // [2][64][72]

    const int tid  = threadIdx.x;
    const int lane = tid & 31;
    const int warp = tid >> 5;
    const int grp  = lane >> 2;
    const int tig  = lane & 3;
    const int b    = blockIdx.y >> 4;
    const int h    = blockIdx.y & 15;
    const int qBase = blockIdx.x * 128;

    const int rA = (lane & 7) + ((lane >> 3) & 1) * 8;
    const int cA = ((lane >> 4) & 1) * 8;
    const int rB = (lane & 7) + ((lane >> 4) & 1) * 8;
    const int cB = ((lane >> 3) & 1) * 8;

    const __half* vth = vt + ((long)(b * H_ + h) * HD_) * S_;

#pragma unroll
    for (int i = 0; i < 4; i++) {
        int idx = tid + i * 256;
        int r   = idx >> 3;
        int q8  = idx & 7;
        cp16(&Qs[r * 72 + q8 * 8],
             &qkh[((long)(b * S_ + qBase + r)) * 2048 + h * 64 + q8 * 8]);
    }
#pragma unroll
    for (int i = 0; i < 2; i++) {
        int idx = tid + i * 256;
        int r   = idx >> 3;
        int q8  = idx & 7;
        cp16(&Ks[r * 72 + q8 * 8],
             &qkh[((long)(b * S_ + r)) * 2048 + 1024 + h * 64 + q8 * 8]);
        cp16(&Vs[r * 72 + q8 * 8], &vth[(long)r * S_ + q8 * 8]);
    }
    CP_COMMIT();

    const __half* Qw = Qs + warp * 16 * 72;

    float m0 = -INFINITY, m1 = -INFINITY, l0 = 0.f, l1 = 0.f;
    float o[8][4];
#pragma unroll
    for (int j = 0; j < 8; j++)
#pragma unroll
        for (int t = 0; t < 4; t++) o[j][t] = 0.f;

    const int nT = S_ / 64;
    for (int t = 0; t < nT; t++) {
        CP_WAIT(0);
        __syncthreads();

        if (t + 1 < nT) {
            __half* Kn = Ks + ((t + 1) & 1) * 4608;
            __half* Vn = Vs + ((t + 1) & 1) * 4608;
            int kt = (t + 1) * 64;
#pragma unroll
            for (int i = 0; i < 2; i++) {
                int idx = tid + i * 256;
                int r   = idx >> 3;
                int q8  = idx & 7;
                cp16(&Kn[r * 72 + q8 * 8],
                     &qkh[((long)(b * S_ + kt + r)) * 2048 + 1024 + h * 64 + q8 * 8]);
                cp16(&Vn[r * 72 + q8 * 8], &vth[(long)r * S_ + kt + q8 * 8]);
            }
        }
        CP_COMMIT();

        const __half* Kc = Ks + (t & 1) * 4608;
        const __half* Vc = Vs + (t & 1) * 4608;

        float s[8][4];
#pragma unroll
        for (int j = 0; j < 8; j++)
#pragma unroll
            for (int tt = 0; tt < 4; tt++) s[j][tt] = 0.f;

#pragma unroll
        for (int kk = 0; kk < 64; kk += 16) {
            uint4 aq = ldsm4(&Qw[rA * 72 + kk + cA]);
#pragma unroll
            for (int jp = 0; jp < 4; jp++) {
                uint4 bk = ldsm4(&Kc[(jp * 16 + rB) * 72 + kk + cB]);
                MMA16(s[2*jp][0],   s[2*jp][1],   s[2*jp][2],   s[2*jp][3],
                      aq.x, aq.y, aq.z, aq.w, bk.x, bk.y);
                MMA16(s[2*jp+1][0], s[2*jp+1][1], s[2*jp+1][2], s[2*jp+1][3],
                      aq.x, aq.y, aq.z, aq.w, bk.z, bk.w);
            }
        }

        float mx0 = -INFINITY, mx1 = -INFINITY;
#pragma unroll
        for (int j = 0; j < 8; j++) {
            mx0 = fmaxf(mx0, fmaxf(s[j][0], s[j][1]));
            mx1 = fmaxf(mx1, fmaxf(s[j][2], s[j][3]));
        }
        mx0 = fmaxf(mx0, __shfl_xor_sync(0xffffffffu, mx0, 1));
        mx0 = fmaxf(mx0, __shfl_xor_sync(0xffffffffu, mx0, 2));
        mx1 = fmaxf(mx1, __shfl_xor_sync(0xffffffffu, mx1, 1));
        mx1 = fmaxf(mx1, __shfl_xor_sync(0xffffffffu, mx1, 2));
        float mn0 = fmaxf(m0, mx0), mn1 = fmaxf(m1, mx1);
        float sc0 = exp2f(m0 - mn0), sc1 = exp2f(m1 - mn1);

        unsigned pr0[8], pr1[8];
        float sum0 = 0.f, sum1 = 0.f;
#pragma unroll
        for (int j = 0; j < 8; j++) {
            float p0 = exp2f(s[j][0] - mn0);
            float p1 = exp2f(s[j][1] - mn0);
            float p2 = exp2f(s[j][2] - mn1);
            float p3 = exp2f(s[j][3] - mn1);
            sum0 += p0 + p1; sum1 += p2 + p3;
            pr0[j] = pack_h2(p0, p1);
            pr1[j] = pack_h2(p2, p3);
        }
        sum0 += __shfl_xor_sync(0xffffffffu, sum0, 1);
        sum0 += __shfl_xor_sync(0xffffffffu, sum0, 2);
        sum1 += __shfl_xor_sync(0xffffffffu, sum1, 1);
        sum1 += __shfl_xor_sync(0xffffffffu, sum1, 2);
        l0 = l0 * sc0 + sum0;
        l1 = l1 * sc1 + sum1;
        m0 = mn0; m1 = mn1;

#pragma unroll
        for (int j = 0; j < 8; j++) {
            o[j][0] *= sc0; o[j][1] *= sc0;
            o[j][2] *= sc1; o[j][3] *= sc1;
        }

#pragma unroll
        for (int kk = 0; kk < 64; kk += 16) {
            unsigned a0 = pr0[kk >> 3];
            unsigned a1 = pr1[kk >> 3];
            unsigned a2 = pr0[(kk >> 3) + 1];
            unsigned a3 = pr1[(kk >> 3) + 1];
#pragma unroll
            for (int jp = 0; jp < 4; jp++) {
                uint4 bv = ldsm4(&Vc[(jp * 16 + rB) * 72 + kk + cB]);
                MMA16(o[2*jp][0],   o[2*jp][1],   o[2*jp][2],   o[2*jp][3],
                      a0, a1, a2, a3, bv.x, bv.y);
                MMA16(o[2*jp+1][0], o[2*jp+1][1], o[2*jp+1][2], o[2*jp+1][3],
                      a0, a1, a2, a3, bv.z, bv.w);
            }
        }
    }

    float inv0 = __frcp_rn(l0), inv1 = __frcp_rn(l1);
    int row0 = qBase + warp * 16 + grp;
#pragma unroll
    for (int j = 0; j < 8; j++) {
        int col = h * 64 + j * 8 + tig * 2;
        *reinterpret_cast<__half2*>(&out[((long)(b * S_ + row0)) * D_ + col]) =
            __floats2half2_rn(o[j][0] * inv0, o[j][1] * inv0);
        *reinterpret_cast<__half2*>(&out[((long)(b * S_ + row0 + 8)) * D_ + col]) =
            __floats2half2_rn(o[j][2] * inv1, o[j][3] * inv1);
    }
}

// ============================================================================
// FP16 NT GEMM (m16n8k16), 4-stage cp.async, ldmatrix, 2 CTAs/SM.
// mode 4: qkv split (Q scaled log2e/8); mode 1: gelu->half;
// mode 2: EX+ada*v; mode 3: EX+ada*(v+evec)
// ============================================================================
#define GSTAGES 4
#define GEMM_SMEM (GSTAGES * 128 * 40 * 2 * 2)   // 81920 B

__global__ void __launch_bounds__(256, 2) gemm_nt_f16(
    const __half* __restrict__ A, const __half* __restrict__ B, void* __restrict__ Cv,
    int K, int lda, int ldb, int ldc,
    int mode, const float* __restrict__ EX, const float* __restrict__ evec,
    const float* __restrict__ ada, int adaOff,
    __half* __restrict__ qh, __half* __restrict__ vth)
{
    extern __shared__ __half hsm[];
    __half* Asm = hsm;
    __half* Bsm = hsm + GSTAGES * 128 * 40;

    const int tid   = threadIdx.x;
    const int lane  = tid & 31;
    const int warp  = tid >> 5;
    const int warpM = warp & 1;
    const int warpN = warp >> 1;
    const int grp   = lane >> 2;
    const int tig   = lane & 3;

    const int rowBase = blockIdx.y * 128;
    const int colBase = blockIdx.x * 128;

    const int rA = (lane & 7) + ((lane >> 3) & 1) * 8;
    const int cA = ((lane >> 4) & 1) * 8;
    const int rB = (lane & 7) + ((lane >> 4) & 1) * 8;
    const int cB = ((lane >> 3) & 1) * 8;

    float acc[4][4][4];
#pragma unroll
    for (int i = 0; i < 4; i++)
#pragma unroll
        for (int j = 0; j < 4; j++)
#pragma unroll
            for (int t = 0; t < 4; t++) acc[i][j][t] = 0.f;

    const int nCh = K >> 5;

    auto load_chunk = [&](int c, int st) {
        __half* as = Asm + st * 128 * 40;
        __half* bs = Bsm + st * 128 * 40;
#pragma unroll
        for (int it = 0; it < 2; it++) {
            int s = tid + it * 256;
            int r = s >> 2;
            int q = s & 3;
            cp16(&as[r * 40 + q * 8], A + (long)(rowBase + r) * lda + c * 32 + q * 8);
            cp16(&bs[r * 40 + q * 8], B + (long)(colBase + r) * ldb + c * 32 + q * 8);
        }
    };

#pragma unroll
    for (int s = 0; s < GSTAGES - 1; s++) {
        if (s < nCh) load_chunk(s, s);
        CP_COMMIT();
    }

    int st = 0;
    for (int c = 0; c < nCh; c++) {
        CP_WAIT(GSTAGES - 2);
        __syncthreads();

        int nc = c + GSTAGES - 1;
        if (nc < nCh) load_chunk(nc, nc % GSTAGES);
        CP_COMMIT();

        const __half* as = Asm + st * 128 * 40;
        const __half* bs = Bsm + st * 128 * 40;
#pragma unroll
        for (int kb = 0; kb < 2; kb++) {
            const int kk = kb * 16;
            uint4 af[4], bf[2];
#pragma unroll
            for (int i = 0; i < 4; i++)
                af[i] = ldsm4(&as[(warpM * 64 + i * 16 + rA) * 40 + kk + cA]);
#pragma unroll
            for (int jp = 0; jp < 2; jp++)
                bf[jp] = ldsm4(&bs[(warpN * 32 + jp * 16 + rB) * 40 + kk + cB]);
#pragma unroll
            for (int i = 0; i < 4; i++) {
                MMA16(acc[i][0][0], acc[i][0][1], acc[i][0][2], acc[i][0][3],
                      af[i].x, af[i].y, af[i].z, af[i].w, bf[0].x, bf[0].y);
                MMA16(acc[i][1][0], acc[i][1][1], acc[i][1][2], acc[i][1][3],
                      af[i].x, af[i].y, af[i].z, af[i].w, bf[0].z, bf[0].w);
                MMA16(acc[i][2][0], acc[i][2][1], acc[i][2][2], acc[i][2][3],
                      af[i].x, af[i].y, af[i].z, af[i].w, bf[1].x, bf[1].y);
                MMA16(acc[i][3][0], acc[i][3][1], acc[i][3][2], acc[i][3][3],
                      af[i].x, af[i].y, af[i].z, af[i].w, bf[1].z, bf[1].w);
            }
        }
        st = (st + 1 == GSTAGES) ? 0 : st + 1;
    }

    // ---- epilogue ----
    float* Cf = (float*)Cv;
    __half* Ch = (__half*)Cv;
#pragma unroll
    for (int i = 0; i < 4; i++) {
#pragma unroll
        for (int j = 0; j < 4; j++) {
            long row = rowBase + warpM * 64 + i * 16 + grp;
            int col = colBase + warpN * 32 + j * 8 + tig * 2;
#pragma unroll
            for (int half_ = 0; half_ < 2; half_++) {
                long r = row + half_ * 8;
                float v0 = acc[i][j][half_ * 2];
                float v1 = acc[i][j][half_ * 2 + 1];
                if (mode == 4) {
                    if (col < 2048) {
                        float qs = (col < 1024) ? 0.18033688011112042f : 1.f;
                        *reinterpret_cast<__half2*>(&qh[r * 2048 + col]) =
                            __floats2half2_rn(v0 * qs, v1 * qs);
                    } else {
                        int hh = (col - 2048) >> 6;
                        int hd = (col - 2048) & 63;
                        int bb = (int)(r >> 11), ss = (int)(r & 2047);
                        __half* base = vth + (((long)(bb * H_ + hh) * HD_ + hd)) * S_ + ss;
                        base[0]  = __float2half_rn(v0);
                        base[S_] = __float2half_rn(v1);
                    }
                } else if (mode == 1) {
                    *reinterpret_cast<__half2*>(&Ch[r * ldc + col]) =
                        __floats2half2_rn(gelu_tanh(v0 + evec[col]),
                                          gelu_tanh(v1 + evec[col + 1]));
                } else if (mode == 2) {
                    int bb = (int)(r >> 11);
                    v0 = EX[r * ldc + col] + ada[bb * 6 * D_ + adaOff + col] * v0;
                    v1 = EX[r * ldc + col + 1] + ada[bb * 6 * D_ + adaOff + col + 1] * v1;
                    *reinterpret_cast<float2*>(&Cf[r * ldc + col]) = make_float2(v0, v1);
                } else {  // mode 3
                    int bb = (int)(r >> 11);
                    v0 = EX[r * ldc + col] + ada[bb * 6 * D_ + adaOff + col] * (v0 + evec[col]);
                    v1 = EX[r * ldc + col + 1] + ada[bb * 6 * D_ + adaOff + col + 1] * (v1 + evec[col + 1]);
                    *reinterpret_cast<float2*>(&Cf[r * ldc + col]) = make_float2(v0, v1);
                }
            }
        }
    }
}

// ---------------- adaLN ----------------
__global__ void __launch_bounds__(256) ada_kernel(
    const float* __restrict__ c, const float* __restrict__ w,
    const float* __restrict__ bias, float* __restrict__ out)
{
    int warp = (blockIdx.x * blockDim.x + threadIdx.x) >> 5;
    int lane = threadIdx.x & 31;
    if (warp >= 6 * D_) return;
    const float* wr = w + (long)warp * D_;
    float s0 = 0.f, s1 = 0.f;
    for (int d = lane; d < D_; d += 32) {
        float wv = wr[d];
        s0 += c[d] * wv;
        s1 += c[D_ + d] * wv;
    }
#pragma unroll
    for (int o = 16; o > 0; o >>= 1) {
        s0 += __shfl_down_sync(0xffffffffu, s0, o);
        s1 += __shfl_down_sync(0xffffffffu, s1, o);
    }
    if (lane == 0) {
        out[warp] = s0 + bias[warp];
        out[6 * D_ + warp] = s1 + bias[warp];
    }
}

// ---------------- LayerNorm + modulate, fp16 output, warp-shuffle reduce ----------------
__global__ void __launch_bounds__(256) ln_mod_kernel(
    const float* __restrict__ x, const float* __restrict__ w,
    const float* __restrict__ ada, int shOff, int scOff, __half* __restrict__ h)
{
    int r = blockIdx.x;
    int b = r >> 11;
    const float* xr = x + (long)r * D_;
    int tid = threadIdx.x;
    int lane = tid & 31;
    int warp = tid >> 5;

    float s = 0.f, ss = 0.f;
    float vals[4];
#pragma unroll
    for (int i = 0; i < 4; i++) {
        float v = xr[tid + i * 256];
        vals[i] = v; s += v; ss += v * v;
    }
#pragma unroll
    for (int o = 16; o > 0; o >>= 1) {
        s  += __shfl_xor_sync(0xffffffffu, s, o);
        ss += __shfl_xor_sync(0xffffffffu, ss, o);
    }
    __shared__ float ws[8], wss[8], fin[2];
    if (lane == 0) { ws[warp] = s; wss[warp] = ss; }
    __syncthreads();
    if (warp == 0 && lane < 8) {
        float a = ws[lane], c2 = wss[lane];
#pragma unroll
        for (int o = 4; o > 0; o >>= 1) {
            a  += __shfl_xor_sync(0xffu, a, o);
            c2 += __shfl_xor_sync(0xffu, c2, o);
        }
        if (lane == 0) { fin[0] = a; fin[1] = c2; }
    }
    __syncthreads();
    float mean = fin[0] * (1.f / D_);
    float var  = fin[1] * (1.f / D_) - mean * mean;
    float inv  = rsqrtf(var + 1e-5f);
    const float* sh = ada + b * 6 * D_ + shOff;
    const float* sc = ada + b * 6 * D_ + scOff;
#pragma unroll
    for (int i = 0; i < 4; i++) {
        int d = tid + i * 256;
        h[(long)r * D_ + d] =
            __float2half_rn((vals[i] - mean) * inv * w[d] * (1.f + sc[d]) + sh[d]);
    }
}

// ---------------- launch ----------------
extern "C" void kernel_launch(void* const* d_in, const int* in_sizes, int n_in,
                              void* d_out, int out_size)
{
    (void)in_sizes; (void)n_in; (void)out_size;
    const float* x       = (const float*)d_in[0];
    const float* c       = (const float*)d_in[3];
    const float* norm1_w = (const float*)d_in[4];
    const float* w_qkv   = (const float*)d_in[5];
    const float* w_out   = (const float*)d_in[6];
    const float* norm2_w = (const float*)d_in[7];
    const float* mlp_w1  = (const float*)d_in[8];
    const float* mlp_b1  = (const float*)d_in[9];
    const float* mlp_w2  = (const float*)d_in[10];
    const float* mlp_b2  = (const float*)d_in[11];
    const float* ada_w   = (const float*)d_in[12];
    const float* ada_b   = (const float*)d_in[13];
    float* out = (float*)d_out;

    float *ada, *x1;
    __half *h, *qkh, *vt, *attn2, *mlp, *wqkv_h, *wout_h, *w1_h, *w2_h;
    cudaGetSymbolAddress((void**)&ada,    g_ada);
    cudaGetSymbolAddress((void**)&h,      g_h);
    cudaGetSymbolAddress((void**)&qkh,    g_qkh);
    cudaGetSymbolAddress((void**)&vt,     g_vt);
    cudaGetSymbolAddress((void**)&attn2,  g_attn2);
    cudaGetSymbolAddress((void**)&x1,     g_x1);
    cudaGetSymbolAddress((void**)&mlp,    g_mlp);
    cudaGetSymbolAddress((void**)&wqkv_h, g_wqkv);
    cudaGetSymbolAddress((void**)&wout_h, g_wout);
    cudaGetSymbolAddress((void**)&w1_h,   g_w1);
    cudaGetSymbolAddress((void**)&w2_h,   g_w2);

    static int inited = 0;
    if (!inited) {
        cudaFuncSetAttribute(flash_attn, cudaFuncAttributeMaxDynamicSharedMemorySize, FA_SMEM);
        cudaFuncSetAttribute(gemm_nt_f16, cudaFuncAttributeMaxDynamicSharedMemorySize, GEMM_SMEM);
        inited = 1;
    }

    // 0. convert weights to fp16
    conv_all<<<12 * D_ * D_ / 4 / 256, 256>>>(w_qkv, w_out, mlp_w1, mlp_w2,
                                              wqkv_h, wout_h, w1_h, w2_h);
    // 1. adaLN projection
    ada_kernel<<<768, 256>>>(c, ada_w, ada_b, ada);
    // 2. LN1 + modulate -> fp16 h
    ln_mod_kernel<<<B_ * S_, 256>>>(x, norm1_w, ada, 0, D_, h);
    // 3. QKV GEMM -> Q(x log2e/8),K fp16 + V^T fp16
    gemm_nt_f16<<<dim3(24, 32), 256, GEMM_SMEM>>>(h, wqkv_h, nullptr, D_,
                                                  D_, D_, 0, 4,
                                                  nullptr, nullptr, nullptr, 0,
                                                  qkh, vt);
    // 4. flash attention (P in registers) -> attn2 fp16
    flash_attn<<<dim3(S_ / 128, B_ * H_), 256, FA_SMEM>>>(qkh, vt, attn2);
    // 5. out-proj + residual1 (fp32 out)
    gemm_nt_f16<<<dim3(8, 32), 256, GEMM_SMEM>>>(attn2, wout_h, x1, D_,
                                                 D_, D_, D_, 2,
                                                 x, nullptr, ada, 2 * D_,
                                                 nullptr, nullptr);
    // 6. LN2 + modulate -> fp16 h
    ln_mod_kernel<<<B_ * S_, 256>>>(x1, norm2_w, ada, 3 * D_, 4 * D_, h);
    // 7. MLP1 + bias + gelu -> fp16 mlp
    gemm_nt_f16<<<dim3(32, 32), 256, GEMM_SMEM>>>(h, w1_h, mlp, D_,
                                                  D_, D_, 4 * D_, 1,
                                                  nullptr, mlp_b1, nullptr, 0,
                                                  nullptr, nullptr);
    // 8. MLP2 + final residual (fp32 out)
    gemm_nt_f16<<<dim3(8, 32), 256, GEMM_SMEM>>>(mlp, w2_h, out, 4 * D_,
                                                 4 * D_, 4 * D_, D_, 3,
                                                 x1, mlp_b2, ada, 5 * D_,
                                                 nullptr, nullptr);
}